// round 2
// baseline (speedup 1.0000x reference)
#include <cuda_runtime.h>
#include <math.h>
#include <math_constants.h>

#define HEAD_DIM   128
#define NUM_Q_HEAD 32
#define NUM_KV_HEAD 8
#define BQ  128
#define BKV 128
#define WINDOW 512
#define CAPV 50.0f
#define EPSV 1e-5f
#define PITCH 132   // 128 + 4 pad: breaks smem bank conflicts for row-major tiles

// scale = 1/sqrt(128)
#define SCALEV 0.08838834764831845f

__global__ __launch_bounds__(256, 1)
void oswa_attn_kernel(const float* __restrict__ q, const float* __restrict__ k,
                      const float* __restrict__ v, const float* __restrict__ go,
                      const float* __restrict__ glse, const float* __restrict__ gq,
                      const float* __restrict__ gk, const int* __restrict__ p_biq,
                      const int* __restrict__ p_bikv, float* __restrict__ out_o,
                      float* __restrict__ out_lse, int seqlen_q, int seqlen_kv)
{
    extern __shared__ float smem[];
    float* sq  = smem;                 // [BQ][PITCH]  normalized q
    float* sk  = sq + BQ * PITCH;      // [BKV][PITCH] normalized k, later raw V
    float* sS  = sk + BKV * PITCH;     // [BQ][PITCH]  logits -> probabilities
    float* sco = sS + BQ * PITCH;      // [BQ] merge coeff old
    float* scb = sco + BQ;             // [BQ] merge coeff new block

    const int h    = blockIdx.x;
    const int b    = blockIdx.y;
    const int kvh  = h / (NUM_Q_HEAD / NUM_KV_HEAD);
    const int tid  = threadIdx.x;
    const int wid  = tid >> 5;
    const int lane = tid & 31;

    const int biq  = p_biq[0];
    const int bikv = p_bikv[0];
    const int row0 = biq  * BQ;
    const int col0 = bikv * BKV;
    const int offs = seqlen_kv - seqlen_q;

    // ---- Phase A: load + GroupRMSNorm q and k rows (warp per row) ----
    #pragma unroll 4
    for (int t = 0; t < 16; ++t) {
        int r = wid * 16 + t;
        // q row
        {
            const float4* qr = (const float4*)(q + ((size_t)((size_t)b * BQ + r) * NUM_Q_HEAD + h) * HEAD_DIM);
            float4 x = qr[lane];
            float ss = x.x*x.x + x.y*x.y + x.z*x.z + x.w*x.w;
            #pragma unroll
            for (int o = 16; o; o >>= 1) ss += __shfl_xor_sync(0xffffffffu, ss, o);
            float rinv = rsqrtf(ss * (1.0f / HEAD_DIM) + EPSV);
            float4 g = ((const float4*)(gq + (size_t)h * HEAD_DIM))[lane];
            float4 y;
            y.x = x.x * rinv * g.x; y.y = x.y * rinv * g.y;
            y.z = x.z * rinv * g.z; y.w = x.w * rinv * g.w;
            *(float4*)(sq + r * PITCH + lane * 4) = y;
        }
        // k row
        {
            const float4* kr = (const float4*)(k + ((size_t)((size_t)b * BKV + r) * NUM_KV_HEAD + kvh) * HEAD_DIM);
            float4 x = kr[lane];
            float ss = x.x*x.x + x.y*x.y + x.z*x.z + x.w*x.w;
            #pragma unroll
            for (int o = 16; o; o >>= 1) ss += __shfl_xor_sync(0xffffffffu, ss, o);
            float rinv = rsqrtf(ss * (1.0f / HEAD_DIM) + EPSV);
            float4 g = ((const float4*)(gk + (size_t)kvh * HEAD_DIM))[lane];
            float4 y;
            y.x = x.x * rinv * g.x; y.y = x.y * rinv * g.y;
            y.z = x.z * rinv * g.z; y.w = x.w * rinv * g.w;
            *(float4*)(sk + r * PITCH + lane * 4) = y;
        }
    }
    __syncthreads();

    // ---- Phase B: S = qn @ kn^T (strided 8x8 register tile per thread) ----
    const int ty = tid >> 4;   // 0..15 -> q rows  ty + 16*i
    const int tx = tid & 15;   // 0..15 -> k cols  tx + 16*j
    float acc[8][8];
    #pragma unroll
    for (int i = 0; i < 8; ++i)
        #pragma unroll
        for (int j = 0; j < 8; ++j) acc[i][j] = 0.0f;

    for (int kk = 0; kk < HEAD_DIM; kk += 4) {
        float4 a[8], bf[8];
        #pragma unroll
        for (int i = 0; i < 8; ++i) a[i]  = *(const float4*)(sq + (ty + 16 * i) * PITCH + kk);
        #pragma unroll
        for (int j = 0; j < 8; ++j) bf[j] = *(const float4*)(sk + (tx + 16 * j) * PITCH + kk);
        #pragma unroll
        for (int i = 0; i < 8; ++i)
            #pragma unroll
            for (int j = 0; j < 8; ++j)
                acc[i][j] += a[i].x * bf[j].x + a[i].y * bf[j].y
                           + a[i].z * bf[j].z + a[i].w * bf[j].w;
    }

    // cap + mask, store logits to smem
    #pragma unroll
    for (int i = 0; i < 8; ++i) {
        int r  = ty + 16 * i;
        int qi = row0 + r;
        int diag = qi + offs;
        #pragma unroll
        for (int j = 0; j < 8; ++j) {
            int c  = tx + 16 * j;
            int kj = col0 + c;
            float L = CAPV * tanhf(acc[i][j] * (SCALEV / CAPV));
            bool ok = (kj <= diag) && (kj >= diag - WINDOW) && (qi < seqlen_q) && (kj < seqlen_kv);
            sS[r * PITCH + c] = ok ? L : -CUDART_INF_F;
        }
    }
    __syncthreads();

    // ---- Phase C: row softmax stats + LSE merge coefficients (warp per row) ----
    for (int t = 0; t < 16; ++t) {
        int r = wid * 16 + t;
        float vv[4];
        float m = -CUDART_INF_F;
        #pragma unroll
        for (int p2 = 0; p2 < 4; ++p2) {
            vv[p2] = sS[r * PITCH + lane + 32 * p2];
            m = fmaxf(m, vv[p2]);
        }
        #pragma unroll
        for (int o = 16; o; o >>= 1) m = fmaxf(m, __shfl_xor_sync(0xffffffffu, m, o));

        float lse;
        if (m == -CUDART_INF_F) {
            #pragma unroll
            for (int p2 = 0; p2 < 4; ++p2) sS[r * PITCH + lane + 32 * p2] = 0.0f;
            lse = -CUDART_INF_F;
        } else {
            float s = 0.0f;
            #pragma unroll
            for (int p2 = 0; p2 < 4; ++p2) s += __expf(vv[p2] - m);
            #pragma unroll
            for (int o = 16; o; o >>= 1) s += __shfl_xor_sync(0xffffffffu, s, o);
            lse = m + logf(s);
            #pragma unroll
            for (int p2 = 0; p2 < 4; ++p2)
                sS[r * PITCH + lane + 32 * p2] = __expf(vv[p2] - lse);
        }

        if (lane == 0) {
            size_t li = ((size_t)b * NUM_Q_HEAD + h) * (size_t)seqlen_q + (size_t)(row0 + r);
            float lo = glse[li];
            float mm = fmaxf(lo, lse);
            float ln, co, cb;
            if (mm == -CUDART_INF_F) { ln = -CUDART_INF_F; co = 0.0f; cb = 0.0f; }
            else {
                ln = mm + logf(expf(lo - mm) + expf(lse - mm));
                co = expf(lo - ln);
                cb = expf(lse - ln);
            }
            sco[r] = co; scb[r] = cb;
            out_lse[li] = ln;
        }
    }

    // load raw V into sk (kn no longer needed)
    #pragma unroll 4
    for (int t = 0; t < 16; ++t) {
        int r = wid * 16 + t;
        const float4* vr = (const float4*)(v + ((size_t)((size_t)b * BKV + r) * NUM_KV_HEAD + kvh) * HEAD_DIM);
        *(float4*)(sk + r * PITCH + lane * 4) = vr[lane];
    }
    __syncthreads();

    // ---- Phase D: O = P @ V ----
    float acc2[8][8];
    #pragma unroll
    for (int i = 0; i < 8; ++i)
        #pragma unroll
        for (int j = 0; j < 8; ++j) acc2[i][j] = 0.0f;

    for (int kk = 0; kk < BKV; kk += 4) {
        float4 p4[8];
        #pragma unroll
        for (int i = 0; i < 8; ++i) p4[i] = *(const float4*)(sS + (ty + 16 * i) * PITCH + kk);
        #pragma unroll
        for (int u = 0; u < 4; ++u) {
            float vv[8];
            #pragma unroll
            for (int j = 0; j < 8; ++j) vv[j] = sk[(kk + u) * PITCH + tx + 16 * j];
            #pragma unroll
            for (int i = 0; i < 8; ++i) {
                float pv = (u == 0) ? p4[i].x : (u == 1) ? p4[i].y : (u == 2) ? p4[i].z : p4[i].w;
                #pragma unroll
                for (int j = 0; j < 8; ++j) acc2[i][j] += pv * vv[j];
            }
        }
    }

    // ---- merged write of the block rows ----
    #pragma unroll
    for (int i = 0; i < 8; ++i) {
        int r  = ty + 16 * i;
        int qi = row0 + r;
        float co = sco[r], cb = scb[r];
        size_t base = ((size_t)((size_t)b * seqlen_q + qi) * NUM_Q_HEAD + h) * HEAD_DIM;
        #pragma unroll
        for (int j = 0; j < 8; ++j) {
            int c = tx + 16 * j;
            float oo = go[base + c];
            out_o[base + c] = co * oo + cb * acc2[i][j];
        }
    }
}

extern "C" void kernel_launch(void* const* d_in, const int* in_sizes, int n_in,
                              void* d_out, int out_size)
{
    const float* q    = (const float*)d_in[0];
    const float* k    = (const float*)d_in[1];
    const float* v    = (const float*)d_in[2];
    const float* go   = (const float*)d_in[3];
    const float* glse = (const float*)d_in[4];
    const float* gq   = (const float*)d_in[5];
    const float* gk   = (const float*)d_in[6];
    const int* biq    = (const int*)d_in[7];
    const int* bikv   = (const int*)d_in[8];

    int b = in_sizes[0] / (BQ * NUM_Q_HEAD * HEAD_DIM);
    size_t o_count   = (size_t)in_sizes[3];
    size_t lse_count = (size_t)in_sizes[4];
    int seqlen_q = (int)(lse_count / ((size_t)b * NUM_Q_HEAD));
    int seqlen_kv = seqlen_q;  // SEQLEN_KV == SEQLEN_Q == 4096 in this problem

    float* out_o   = (float*)d_out;
    float* out_lse = out_o + o_count;

    // pass-through copies (the attention kernel then overwrites the block rows)
    cudaMemcpyAsync(out_o,   go,   o_count   * sizeof(float), cudaMemcpyDeviceToDevice, 0);
    cudaMemcpyAsync(out_lse, glse, lse_count * sizeof(float), cudaMemcpyDeviceToDevice, 0);

    const size_t SMEM = (size_t)(3 * BQ * PITCH + 2 * BQ) * sizeof(float);
    cudaFuncSetAttribute(oswa_attn_kernel, cudaFuncAttributeMaxDynamicSharedMemorySize, (int)SMEM);

    dim3 grid(NUM_Q_HEAD, b);
    oswa_attn_kernel<<<grid, 256, SMEM>>>(q, k, v, go, glse, gq, gk, biq, bikv,
                                          out_o, out_lse, seqlen_q, seqlen_kv);
}